// round 1
// baseline (speedup 1.0000x reference)
#include <cuda_runtime.h>
#include <cuda_bf16.h>
#include <cstdint>
#include <cstddef>

#define BB 64
#define TT 2048
#define DD 256
#define VV 256

// ---------------- device scratch (no cudaMalloc allowed) ----------------
__device__ float g_EWx[VV * DD];          // E @ Wx_w^T   [v][e]
__device__ float g_G[VV * DD];            // sigmoid(E @ Wz_w^T) [v][e]
__device__ float g_y[(size_t)BB * TT * DD]; // gated hidden states [b,t,e]

// ---------------- helpers ----------------
__device__ __forceinline__ uint32_t smem_u32(const void* p) {
    uint32_t a;
    asm("{ .reg .u64 t; cvta.to.shared.u64 t, %1; cvt.u32.u64 %0, t; }"
        : "=r"(a) : "l"(p));
    return a;
}

// ================= Kernel 1: tiny projection tables =================
// EWx[v][e] = sum_d E[v][d] * Wx_w[e][d];   G[v][e] = sigmoid(sum_d E[v][d]*Wz_w[e][d])
__global__ __launch_bounds__(256) void proj_kernel(
    const float* __restrict__ E,
    const float* __restrict__ Wx,
    const float* __restrict__ Wz)
{
    __shared__ __align__(16) float4 er[DD / 4];
    const int v = blockIdx.x;
    const int e = threadIdx.x;
    if (e < DD / 4) er[e] = ((const float4*)(E + (size_t)v * DD))[e];
    __syncthreads();

    const float4* wx4 = (const float4*)(Wx + (size_t)e * DD);
    const float4* wz4 = (const float4*)(Wz + (size_t)e * DD);
    float ax = 0.f, az = 0.f;
#pragma unroll 8
    for (int i = 0; i < DD / 4; i++) {
        float4 ev = er[i];
        float4 a = wx4[i];
        float4 b = wz4[i];
        ax += ev.x * a.x + ev.y * a.y + ev.z * a.z + ev.w * a.w;
        az += ev.x * b.x + ev.y * b.y + ev.z * b.z + ev.w * b.w;
    }
    g_EWx[v * DD + e] = ax;
    g_G[v * DD + e]   = 1.f / (1.f + expf(-az));
}

// ================= Kernel 2: recurrence =================
// Cluster of 2 CTAs per batch chain. grid = 128 CTAs, 512 threads.
// CTA rank r owns output rows eg = r*128 .. r*128+127 of Wh, fully in registers:
// thread t: e_loc = t>>2, q = t&3, holds Wh[eg][64q .. 64q+63] (64 fp32 regs).
// h lives double-buffered in shared memory (chunk-padded layout to kill bank
// conflicts: element k stored at word k + 4*(k>>6)). Each step the q==0 lane of
// each 4-lane group writes its new h value to its own smem AND to the peer CTA
// via st.shared::cluster; barrier.cluster separates steps.
#define HPAD 272   // 256 + 4*4 chunk padding

__global__ void __cluster_dims__(2, 1, 1) __launch_bounds__(512, 1)
rnn_kernel(const int* __restrict__ tokens, const float* __restrict__ Wh)
{
    __shared__ int stok[TT];
    __shared__ __align__(16) float hbuf[2][HPAD];

    const int tid  = threadIdx.x;
    const int bx   = blockIdx.x;
    const int b    = bx >> 1;
    const int rank = bx & 1;
    const int q    = tid & 3;
    const int eloc = tid >> 2;
    const int eg   = rank * 128 + eloc;

    // ---- load my 64 weights into registers ----
    float w[64];
    const float* wrow = Wh + (size_t)eg * DD + q * 64;
#pragma unroll
    for (int j = 0; j < 64; j++) w[j] = wrow[j];

    // ---- tokens for this chain into smem ----
    for (int i = tid; i < TT; i += 512) stok[i] = tokens[(size_t)b * TT + i];

    // ---- h0 = 0 (both parity buffers) ----
    if (tid < HPAD) { hbuf[0][tid] = 0.f; hbuf[1][tid] = 0.f; }

    // all smem (incl. peer's) ready before anyone writes remotely
    asm volatile("barrier.cluster.arrive.aligned;" ::: "memory");
    asm volatile("barrier.cluster.wait.aligned;"   ::: "memory");

    int p = 0;
    float* ybase = g_y + (size_t)b * TT * DD;

    for (int t = 0; t < TT; t++) {
        const int tok = stok[t];

        // prefetch gather rows early (L2-resident tables); only q==0 lanes use them
        float wx = 0.f, gg = 0.f;
        if (q == 0) {
            wx = __ldg(&g_EWx[tok * DD + eg]);
            gg = __ldg(&g_G[tok * DD + eg]);
        }

        // partial dot: k in [64q, 64q+64)
        float acc = 0.f;
        const float4* hb = (const float4*)(&hbuf[p][68 * q]);
#pragma unroll
        for (int i = 0; i < 16; i++) {
            float4 hv = hb[i];
            acc += w[4 * i + 0] * hv.x;
            acc += w[4 * i + 1] * hv.y;
            acc += w[4 * i + 2] * hv.z;
            acc += w[4 * i + 3] * hv.w;
        }
        // reduce the 4 k-partials (lanes 4e..4e+3)
        acc += __shfl_xor_sync(0xffffffffu, acc, 1);
        acc += __shfl_xor_sync(0xffffffffu, acc, 2);

        const int np = p ^ 1;
        if (q == 0) {
            float hn = tanhf(acc + wx);
            const int hi = eg + ((eg >> 6) << 2);   // chunk-padded index
            hbuf[np][hi] = hn;
            // mirror into peer CTA's buffer
            uint32_t laddr = smem_u32(&hbuf[np][hi]);
            uint32_t raddr;
            asm("mapa.shared::cluster.u32 %0, %1, %2;"
                : "=r"(raddr) : "r"(laddr), "r"(rank ^ 1));
            asm volatile("st.shared::cluster.f32 [%0], %1;"
                         :: "r"(raddr), "f"(hn) : "memory");
            // gated output
            ybase[(size_t)t * DD + eg] = hn * gg;
        }

        // step barrier: release my remote/local h writes, acquire peer's
        asm volatile("barrier.cluster.arrive.aligned;" ::: "memory");
        asm volatile("barrier.cluster.wait.aligned;"   ::: "memory");
        p = np;
    }
}

// ================= Kernel 3: head GEMM =================
// logits[r][v] = sum_d y[r][d] * E[v][d].  32-row tile in smem, thread = v.
__global__ __launch_bounds__(256) void head_kernel(
    const float* __restrict__ E,
    float* __restrict__ out)
{
    __shared__ __align__(16) float ys[32 * DD];   // 32 KB

    const int t = threadIdx.x;                    // v index
    const size_t rowbase = (size_t)blockIdx.x * 32;

    // load y tile (coalesced float4)
    const float4* ysrc = (const float4*)(g_y + rowbase * DD);
    float4* ydst = (float4*)ys;
#pragma unroll
    for (int i = 0; i < 8; i++) ydst[t + 256 * i] = ysrc[t + 256 * i];
    __syncthreads();

    float acc[32];
#pragma unroll
    for (int m = 0; m < 32; m++) acc[m] = 0.f;

    const float4* e4 = (const float4*)(E + (size_t)t * DD);
#pragma unroll 4
    for (int d4 = 0; d4 < DD / 4; d4++) {
        float4 w4 = e4[d4];
#pragma unroll
        for (int m = 0; m < 32; m++) {
            float4 yv = *(const float4*)(ys + m * DD + d4 * 4);
            acc[m] += w4.x * yv.x + w4.y * yv.y + w4.z * yv.z + w4.w * yv.w;
        }
    }

    float* orow = out + rowbase * VV;
#pragma unroll
    for (int m = 0; m < 32; m++) orow[(size_t)m * VV + t] = acc[m];
}

// ================= launch =================
extern "C" void kernel_launch(void* const* d_in, const int* in_sizes, int n_in,
                              void* d_out, int out_size)
{
    const int*   tokens = (const int*)  d_in[0];
    const float* E      = (const float*)d_in[1];
    const float* Wx     = (const float*)d_in[2];
    const float* Wh     = (const float*)d_in[3];
    const float* Wz     = (const float*)d_in[4];
    float* out = (float*)d_out;

    proj_kernel<<<VV, 256>>>(E, Wx, Wz);
    rnn_kernel<<<BB * 2, 512>>>(tokens, Wh);
    head_kernel<<<(BB * TT) / 32, 256>>>(E, out);
}

// round 2
// speedup vs baseline: 1.1989x; 1.1989x over previous
#include <cuda_runtime.h>
#include <cuda_bf16.h>
#include <cstdint>
#include <cstddef>

#define BB 64
#define TT 2048
#define DD 256
#define VV 256

// ---------------- device scratch (no cudaMalloc allowed) ----------------
__device__ __align__(16) float g_EWx[VV * DD];            // E @ Wx_w^T   [v][e]
__device__ __align__(16) float g_G[VV * DD];              // sigmoid(E @ Wz_w^T) [v][e]
__device__ __align__(16) float g_y[(size_t)BB * TT * DD]; // gated hidden states [b,t,e]

// ---------------- helpers ----------------
__device__ __forceinline__ uint32_t smem_u32(const void* p) {
    uint32_t a;
    asm("{ .reg .u64 t; cvta.to.shared.u64 t, %1; cvt.u32.u64 %0, t; }"
        : "=r"(a) : "l"(p));
    return a;
}

// packed fp32x2 FMA: acc = a*b + acc  (full fp32 precision, 2 MACs / instr)
#define FFMA2(acc, a, b) \
    asm("fma.rn.f32x2 %0, %1, %2, %0;" : "+l"(acc) : "l"(a), "l"(b))

__device__ __forceinline__ float f32x2_hsum(unsigned long long a,
                                            unsigned long long b) {
    unsigned long long s;
    asm("add.rn.f32x2 %0, %1, %2;" : "=l"(s) : "l"(a), "l"(b));
    float lo, hi;
    asm("mov.b64 {%0, %1}, %2;" : "=f"(lo), "=f"(hi) : "l"(s));
    return lo + hi;
}

__device__ __forceinline__ void mbar_init(uint32_t addr, uint32_t count) {
    asm volatile("mbarrier.init.shared.b64 [%0], %1;" :: "r"(addr), "r"(count)
                 : "memory");
}

// wait with acquire at cluster scope (we consume peer-CTA DSMEM stores)
__device__ __forceinline__ void mbar_wait_cluster(uint32_t addr, uint32_t parity) {
    uint32_t done;
    asm volatile(
        "{\n\t.reg .pred p;\n\t"
        "mbarrier.try_wait.parity.acquire.cluster.shared::cta.b64 p, [%1], %2;\n\t"
        "selp.b32 %0, 1, 0, p;\n\t}"
        : "=r"(done) : "r"(addr), "r"(parity) : "memory");
    if (!done) {
        asm volatile(
            "{\n\t.reg .pred P1;\n\t"
            "W_%=:\n\t"
            "mbarrier.try_wait.parity.acquire.cluster.shared::cta.b64 P1, [%0], %1, 0x989680;\n\t"
            "@P1 bra.uni D_%=;\n\t"
            "bra.uni W_%=;\n\t"
            "D_%=:\n\t}"
            :: "r"(addr), "r"(parity) : "memory");
    }
}

// ================= Kernel 1: tiny projection tables =================
__global__ __launch_bounds__(256) void proj_kernel(
    const float* __restrict__ E,
    const float* __restrict__ Wx,
    const float* __restrict__ Wz)
{
    __shared__ __align__(16) float4 er[DD / 4];
    const int v = blockIdx.x;
    const int e = threadIdx.x;
    if (e < DD / 4) er[e] = ((const float4*)(E + (size_t)v * DD))[e];
    __syncthreads();

    const float4* wx4 = (const float4*)(Wx + (size_t)e * DD);
    const float4* wz4 = (const float4*)(Wz + (size_t)e * DD);
    float ax0 = 0.f, ax1 = 0.f, az0 = 0.f, az1 = 0.f;
#pragma unroll 8
    for (int i = 0; i < DD / 4; i++) {
        float4 ev = er[i];
        float4 a = wx4[i];
        float4 b = wz4[i];
        ax0 += ev.x * a.x + ev.y * a.y;
        ax1 += ev.z * a.z + ev.w * a.w;
        az0 += ev.x * b.x + ev.y * b.y;
        az1 += ev.z * b.z + ev.w * b.w;
    }
    g_EWx[v * DD + e] = ax0 + ax1;
    g_G[v * DD + e]   = 1.f / (1.f + expf(-(az0 + az1)));
}

// ================= Kernel 2: recurrence =================
// Cluster of 2 CTAs per batch chain; 128 clusters total, 512 threads each.
// CTA rank r holds Wh rows [r*128, r*128+128) in registers as f32x2 pairs.
// Per step: f32x2 dot partials -> shfl reduce -> tanh -> local store + DSMEM
// mirror to peer + remote mbarrier arrive; peer waits mbarrier (no cluster
// barrier). wx/gate gathers prefetched one step ahead.
#define HPAD 272   // 256 + 4*4 chunk padding (64-float chunks at stride 68)

__global__ void __cluster_dims__(2, 1, 1) __launch_bounds__(512, 1)
rnn_kernel(const int* __restrict__ tokens, const float* __restrict__ Wh)
{
    __shared__ int stok[TT];
    __shared__ __align__(16) float hbuf[2][HPAD];
    __shared__ __align__(8) unsigned long long mb[2];

    const int tid  = threadIdx.x;
    const int bx   = blockIdx.x;
    const int b    = bx >> 1;
    const int rank = bx & 1;
    const int q    = tid & 3;
    const int eloc = tid >> 2;
    const int eg   = rank * 128 + eloc;

    // ---- my 64 weights as 32 f32x2 registers ----
    unsigned long long wp[32];
    {
        const ulonglong2* wsrc =
            (const ulonglong2*)(Wh + (size_t)eg * DD + q * 64);
#pragma unroll
        for (int j = 0; j < 16; j++) {
            ulonglong2 v = wsrc[j];
            wp[2 * j]     = v.x;
            wp[2 * j + 1] = v.y;
        }
    }

    for (int i = tid; i < TT; i += 512) stok[i] = tokens[(size_t)b * TT + i];
    if (tid < HPAD) { hbuf[0][tid] = 0.f; hbuf[1][tid] = 0.f; }
    if (tid == 0) {
        mbar_init(smem_u32(&mb[0]), 128);
        mbar_init(smem_u32(&mb[1]), 128);
    }

    // cluster barrier: smem init (tokens, h0, mbarriers) visible everywhere
    asm volatile("barrier.cluster.arrive.aligned;" ::: "memory");
    asm volatile("barrier.cluster.wait.aligned;"   ::: "memory");

    const int hi = eg + ((eg >> 6) << 2);   // chunk-padded index
    // remote (peer-CTA) addresses for both parities
    uint32_t rh[2], rmb[2];
    {
        uint32_t l0 = smem_u32(&hbuf[0][hi]);
        uint32_t l1 = smem_u32(&hbuf[1][hi]);
        uint32_t m0 = smem_u32(&mb[0]);
        uint32_t m1 = smem_u32(&mb[1]);
        const int peer = rank ^ 1;
        asm("mapa.shared::cluster.u32 %0, %1, %2;" : "=r"(rh[0]) : "r"(l0), "r"(peer));
        asm("mapa.shared::cluster.u32 %0, %1, %2;" : "=r"(rh[1]) : "r"(l1), "r"(peer));
        asm("mapa.shared::cluster.u32 %0, %1, %2;" : "=r"(rmb[0]) : "r"(m0), "r"(peer));
        asm("mapa.shared::cluster.u32 %0, %1, %2;" : "=r"(rmb[1]) : "r"(m1), "r"(peer));
    }
    const uint32_t lmb0 = smem_u32(&mb[0]);
    const uint32_t lmb1 = smem_u32(&mb[1]);

    float* ybase = g_y + (size_t)b * TT * DD;

    // prefetch step-0 gathers
    float wx_n = 0.f, gg_n = 0.f;
    if (q == 0) {
        const int tok0 = stok[0];
        wx_n = __ldg(&g_EWx[tok0 * DD + eg]);
        gg_n = __ldg(&g_G[tok0 * DD + eg]);
    }

    int p = 0;
    uint32_t ph0 = 0, ph1 = 0;

    for (int t = 0; t < TT; t++) {
        const float wx = wx_n, gg = gg_n;
        if (q == 0 && t + 1 < TT) {
            const int tokn = stok[t + 1];
            wx_n = __ldg(&g_EWx[tokn * DD + eg]);
            gg_n = __ldg(&g_G[tokn * DD + eg]);
        }

        // partial dot over k in [64q, 64q+64) with packed f32x2
        unsigned long long acc_a = 0ull, acc_b = 0ull;
        const ulonglong2* hb = (const ulonglong2*)(&hbuf[p][68 * q]);
#pragma unroll
        for (int i = 0; i < 16; i++) {
            ulonglong2 h2 = hb[i];
            FFMA2(acc_a, wp[2 * i],     h2.x);
            FFMA2(acc_b, wp[2 * i + 1], h2.y);
        }
        float acc = f32x2_hsum(acc_a, acc_b);
        acc += __shfl_xor_sync(0xffffffffu, acc, 1);
        acc += __shfl_xor_sync(0xffffffffu, acc, 2);

        const int np = p ^ 1;
        if (q == 0) {
            const float hn = tanhf(acc + wx);
            hbuf[np][hi] = hn;
            // mirror into peer CTA then signal its mbarrier (release@cluster)
            asm volatile("st.shared::cluster.f32 [%0], %1;"
                         :: "r"(rh[np]), "f"(hn) : "memory");
            asm volatile("mbarrier.arrive.release.cluster.shared::cluster.b64 _, [%0];"
                         :: "r"(rmb[np]) : "memory");
            ybase[(size_t)t * DD + eg] = hn * gg;
        }

        __syncthreads();                         // local h writes visible
        if (np == 0) { mbar_wait_cluster(lmb0, ph0); ph0 ^= 1; }
        else         { mbar_wait_cluster(lmb1, ph1); ph1 ^= 1; }
        p = np;
    }
}

// ================= Kernel 3: head GEMM =================
// logits[r][v] = sum_d y[r][d] * E[v][d].
// 64x64 tile per CTA, 4x4 micro-tile per thread, f32x2 pairs along k.
#define HKS 68   // 64 + 4 pad (16B-aligned rows, conflict-limited)

__global__ __launch_bounds__(256) void head_kernel(
    const float* __restrict__ E,
    float* __restrict__ out)
{
    __shared__ __align__(16) float ys[64 * HKS];
    __shared__ __align__(16) float es[64 * HKS];

    const int tid = threadIdx.x;
    const int tx  = tid & 15;     // v-lane: cols tx, tx+16, tx+32, tx+48
    const int ty  = tid >> 4;     // row group: rows ty*4 .. ty*4+3
    const size_t rowbase = (size_t)(blockIdx.x >> 2) * 64;
    const int vbase = (blockIdx.x & 3) * 64;

    unsigned long long acc[4][4];
#pragma unroll
    for (int r = 0; r < 4; r++)
#pragma unroll
        for (int c = 0; c < 4; c++) acc[r][c] = 0ull;

    for (int kc = 0; kc < 4; kc++) {
        const int k0 = kc * 64;
        // stage y tile [64 rows x 64 k] and E tile [64 v x 64 k], row-major
        for (int i = tid; i < 1024; i += 256) {
            const int m = i >> 4, kk = i & 15;
            *(float4*)(ys + m * HKS + kk * 4) =
                *(const float4*)(g_y + (rowbase + m) * DD + k0 + kk * 4);
            *(float4*)(es + m * HKS + kk * 4) =
                *(const float4*)(E + (size_t)(vbase + m) * DD + k0 + kk * 4);
        }
        __syncthreads();

#pragma unroll
        for (int k4 = 0; k4 < 16; k4++) {
            ulonglong2 yv[4], ev[4];
#pragma unroll
            for (int r = 0; r < 4; r++)
                yv[r] = *(const ulonglong2*)(ys + (ty * 4 + r) * HKS + k4 * 4);
#pragma unroll
            for (int c = 0; c < 4; c++)
                ev[c] = *(const ulonglong2*)(es + (tx + 16 * c) * HKS + k4 * 4);
#pragma unroll
            for (int r = 0; r < 4; r++)
#pragma unroll
                for (int c = 0; c < 4; c++) {
                    FFMA2(acc[r][c], yv[r].x, ev[c].x);
                    FFMA2(acc[r][c], yv[r].y, ev[c].y);
                }
        }
        __syncthreads();
    }

#pragma unroll
    for (int r = 0; r < 4; r++) {
        float* orow = out + (rowbase + ty * 4 + r) * VV + vbase;
#pragma unroll
        for (int c = 0; c < 4; c++) {
            float lo, hi;
            asm("mov.b64 {%0, %1}, %2;" : "=f"(lo), "=f"(hi) : "l"(acc[r][c]));
            orow[tx + 16 * c] = lo + hi;
        }
    }
}

// ================= launch =================
extern "C" void kernel_launch(void* const* d_in, const int* in_sizes, int n_in,
                              void* d_out, int out_size)
{
    const int*   tokens = (const int*)  d_in[0];
    const float* E      = (const float*)d_in[1];
    const float* Wx     = (const float*)d_in[2];
    const float* Wh     = (const float*)d_in[3];
    const float* Wz     = (const float*)d_in[4];
    float* out = (float*)d_out;

    proj_kernel<<<VV, 256>>>(E, Wx, Wz);
    rnn_kernel<<<BB * 2, 512>>>(tokens, Wh);
    head_kernel<<<(BB * TT / 64) * (VV / 64), 256>>>(E, out);
}